// round 5
// baseline (speedup 1.0000x reference)
#include <cuda_runtime.h>
#include <cstdint>

// Depthwise 3D conv 3x3x3, SAME, stride 1.
// x: (4,16,112,112,64) f32 NDHWC ; w: (3,3,3,1,64) f32
//
// R3: d-rolling kernel. Thread owns (n, ht, wt, c4) and streams all 16 input
// D-slices exactly once; three rolling accumulator sets (d=s-1,s,s+1) receive
// each slice's contribution via the matching kd weight plane. Kills the 3x
// kd re-read of the input (L1 amp 9x -> 4x). All 27 weight float4 in regs.

#define C4          16
#define W_DIM       112
#define H_DIM       112
#define D_DIM       16
#define N_DIM       4
#define HS          2
#define WS          2
#define WT          (W_DIM / WS)     // 56
#define HT          (H_DIM / HS)     // 56
#define TILES       (WT * HT)        // 3136
#define TPB_TILES   8
#define TPB         128
#define ROW_STRIDE   (W_DIM * C4)            // f4 per H-row
#define SLICE_STRIDE ((size_t)H_DIM * W_DIM * C4)  // f4 per D-slice

__device__ __forceinline__ void fma2(unsigned long long& d,
                                     unsigned long long a,
                                     unsigned long long b) {
    asm("fma.rn.f32x2 %0, %1, %2, %0;" : "+l"(d) : "l"(a), "l"(b));
}

// Apply the FMAs of input rows [r0, r0+1] (already in rb) against weight
// plane kd into accumulator set A.
#define APPLY_ROWS(A, KD, R0)                                              \
    _Pragma("unroll")                                                      \
    for (int rr = 0; rr < 2; rr++) {                                       \
        const int r = (R0) + rr;                                           \
        _Pragma("unroll")                                                  \
        for (int oh = 0; oh < HS; oh++) {                                  \
            const int kh = r - oh;                                         \
            if (kh >= 0 && kh < 3) {                                       \
                _Pragma("unroll")                                          \
                for (int ow = 0; ow < WS; ow++) {                          \
                    _Pragma("unroll")                                      \
                    for (int kw = 0; kw < 3; kw++) {                       \
                        fma2((A)[oh][ow].x, rb[rr][ow + kw].x,             \
                             wgt[KD][kh][kw].x);                           \
                        fma2((A)[oh][ow].y, rb[rr][ow + kw].y,             \
                             wgt[KD][kh][kw].y);                           \
                    }                                                      \
                }                                                          \
            }                                                              \
        }                                                                  \
    }

// Process one input slice s: load 4 halo rows (2-row batches), apply to the
// three rolling acc sets. CUR = acc[s%3] (d=s), NXT = acc[(s+1)%3] (d=s+1),
// PRV = acc[(s+2)%3] (d=s-1).
#define DO_SLICE(S_EXPR, I_CUR, I_NXT, I_PRV, DO_PRV, DO_STORE)            \
    {                                                                      \
        const int s = (S_EXPR);                                            \
        const ulonglong2* xs = xbase + (size_t)s * SLICE_STRIDE;           \
        ulonglong2 rb[2][WS + 2];                                          \
        _Pragma("unroll")                                                  \
        for (int half = 0; half < 2; half++) {                             \
            _Pragma("unroll")                                              \
            for (int rr = 0; rr < 2; rr++) {                               \
                const int r = half * 2 + rr;                               \
                const ulonglong2* p =                                      \
                    xs + (ptrdiff_t)(h0 + r - 1) * ROW_STRIDE;             \
                const bool hv = hvalid[r];                                 \
                rb[rr][0] = (hv && lv) ? p[0] : zero2;                     \
                rb[rr][1] = hv ? p[C4] : zero2;                            \
                rb[rr][2] = hv ? p[2 * C4] : zero2;                        \
                rb[rr][3] = (hv && rv) ? p[3 * C4] : zero2;                \
            }                                                              \
            APPLY_ROWS(acc[I_NXT], 0, half * 2)                            \
            APPLY_ROWS(acc[I_CUR], 1, half * 2)                            \
            if (DO_PRV) { APPLY_ROWS(acc[I_PRV], 2, half * 2) }            \
        }                                                                  \
        if (DO_STORE) {                                                    \
            ulonglong2* o = ob + (size_t)(s - 1) * SLICE_STRIDE;           \
            _Pragma("unroll")                                              \
            for (int i = 0; i < HS; i++)                                   \
                _Pragma("unroll")                                          \
                for (int j = 0; j < WS; j++) {                             \
                    o[i * ROW_STRIDE + j * C4] = acc[I_PRV][i][j];         \
                    acc[I_PRV][i][j] = zero2;                              \
                }                                                          \
        }                                                                  \
    }

__global__ void __launch_bounds__(TPB, 2)
dwconv3d_kernel(const ulonglong2* __restrict__ xin,
                const ulonglong2* __restrict__ win,
                ulonglong2* __restrict__ out)
{
    const int tx   = threadIdx.x;
    const int c4   = tx & (C4 - 1);
    const int tile = blockIdx.x * TPB_TILES + (tx >> 4);
    const int ht   = tile / WT;
    const int wt   = tile - ht * WT;
    const int n    = blockIdx.y;
    const int h0   = ht * HS;
    const int w0   = wt * WS;

    const bool lv = (wt != 0);
    const bool rv = (wt != WT - 1);
    bool hvalid[HS + 2];
    #pragma unroll
    for (int r = 0; r < HS + 2; r++) {
        const int ih = h0 + r - 1;
        hvalid[r] = (ih >= 0) && (ih < H_DIM);
    }

    // all 27 weight float4 in registers
    const ulonglong2* wb = win + c4;
    ulonglong2 wgt[3][3][3];
    #pragma unroll
    for (int kd = 0; kd < 3; kd++)
        #pragma unroll
        for (int kh = 0; kh < 3; kh++)
            #pragma unroll
            for (int kw = 0; kw < 3; kw++)
                wgt[kd][kh][kw] = wb[((kd * 3 + kh) * 3 + kw) * C4];

    // base of input at (n, d=0, h=0, w=w0-1, c4)
    const ulonglong2* xbase = xin
        + (size_t)n * D_DIM * SLICE_STRIDE
        + (ptrdiff_t)(w0 - 1) * C4 + c4;
    // base of output at (n, d=0, h=h0, w=w0, c4)
    ulonglong2* ob = out
        + (size_t)n * D_DIM * SLICE_STRIDE
        + ((size_t)h0 * W_DIM + w0) * C4 + c4;

    const ulonglong2 zero2 = make_ulonglong2(0ull, 0ull);

    ulonglong2 acc[3][HS][WS];
    #pragma unroll
    for (int q = 0; q < 3; q++)
        #pragma unroll
        for (int i = 0; i < HS; i++)
            #pragma unroll
            for (int j = 0; j < WS; j++)
                acc[q][i][j] = zero2;

    // s = 0 peeled: cur=acc[0] (d=0, w[1]), nxt=acc[1] (d=1, w[0]); no prev.
    DO_SLICE(0, 0, 1, 2, false, false)

    // s = 1..15 : 5 iterations unrolled x3 so s%3 is compile-time.
    #pragma unroll 1
    for (int t = 0; t < 5; t++) {
        const int sb = 1 + 3 * t;
        DO_SLICE(sb + 0, 1, 2, 0, true, true)   // s%3==1
        DO_SLICE(sb + 1, 2, 0, 1, true, true)   // s%3==2
        DO_SLICE(sb + 2, 0, 1, 2, true, true)   // s%3==0
    }

    // d = 15 = cur at s=15 = acc[0]
    {
        ulonglong2* o = ob + (size_t)15 * SLICE_STRIDE;
        #pragma unroll
        for (int i = 0; i < HS; i++)
            #pragma unroll
            for (int j = 0; j < WS; j++)
                o[i * ROW_STRIDE + j * C4] = acc[0][i][j];
    }
}

extern "C" void kernel_launch(void* const* d_in, const int* in_sizes, int n_in,
                              void* d_out, int out_size) {
    const ulonglong2* x = (const ulonglong2*)d_in[0];
    const ulonglong2* w = (const ulonglong2*)d_in[1];
    ulonglong2* o = (ulonglong2*)d_out;

    dim3 grid(TILES / TPB_TILES, N_DIM);   // (392, 4)
    dwconv3d_kernel<<<grid, TPB>>>(x, w, o);
}

// round 6
// speedup vs baseline: 1.4933x; 1.4933x over previous
#include <cuda_runtime.h>
#include <cstdint>

// Depthwise 3D conv 3x3x3, SAME, stride 1.
// x: (4,16,112,112,64) f32 NDHWC ; w: (3,3,3,1,64) f32
//
// R5: latency-hiding build. float2 channel vectors (C=64 -> 32 c2 lanes =
// exactly one warp per pixel, 256B coalesced LDG.64 per step). Warp tile =
// 2(H) x 7(W); per-thread regs ~80 -> __launch_bounds__(128,6) = 24 warps/SM.
// kd-outer with 9-wide batched row loads for MLP. Packed fma.rn.f32x2.

typedef unsigned long long u64;

#define W_DIM   112
#define H_DIM   112
#define D_DIM   16
#define N_DIM   4
#define C2      32                  // float2 channel groups = warp lanes
#define WS      7
#define HS      2
#define WSEG    (W_DIM / WS)        // 16
#define HPAIR   (H_DIM / HS)        // 56
#define WPB     4                   // warps per block
#define TPB     (WPB * 32)          // 128

#define ROW_F2    (W_DIM * C2)              // 3584 u64 per H-row
#define SLICE_F2  (H_DIM * W_DIM * C2)      // per D-slice
#define IMG_F2    (D_DIM * SLICE_F2)        // per batch n

__device__ __forceinline__ void fma2(u64& d, u64 a, u64 b) {
    asm("fma.rn.f32x2 %0, %1, %2, %0;" : "+l"(d) : "l"(a), "l"(b));
}

__global__ void __launch_bounds__(TPB, 6)
dwconv3d_kernel(const u64* __restrict__ xin,
                const u64* __restrict__ win,
                u64* __restrict__ out)
{
    const int lane = threadIdx.x & 31;
    const int gw   = blockIdx.x * WPB + (threadIdx.x >> 5);

    const int wseg = gw & (WSEG - 1);
    int t          = gw >> 4;
    const int hp   = t % HPAIR;
    t             /= HPAIR;
    const int d    = t & (D_DIM - 1);
    const int n    = t >> 4;

    const int h0 = hp * HS;
    const int w0 = wseg * WS;
    const bool lv = (wseg != 0);
    const bool rv = (wseg != WSEG - 1);

    const u64* xn = xin + (size_t)n * IMG_F2 + lane;
    const u64* wb = win + lane;

    u64 acc[HS][WS];
    #pragma unroll
    for (int i = 0; i < HS; i++)
        #pragma unroll
        for (int j = 0; j < WS; j++)
            acc[i][j] = 0ull;

    #pragma unroll
    for (int kd = 0; kd < 3; kd++) {
        const int id = d + kd - 1;
        if (id < 0 || id >= D_DIM) continue;      // warp-uniform branch

        // 9 weight float2 for this kd plane (L1-resident)
        u64 wgt[3][3];
        #pragma unroll
        for (int kh = 0; kh < 3; kh++)
            #pragma unroll
            for (int kw = 0; kw < 3; kw++)
                wgt[kh][kw] = wb[((kd * 3 + kh) * 3 + kw) * C2];

        const u64* xs = xn + (size_t)id * SLICE_F2;

        #pragma unroll
        for (int r = 0; r < HS + 2; r++) {
            const int ih = h0 + r - 1;
            const bool hv = (ih >= 0) && (ih < H_DIM);
            const u64* p = xs + ((ptrdiff_t)ih * W_DIM + (w0 - 1)) * C2;

            // batched 9-wide row load (high MLP), halo predicated
            u64 row[WS + 2];
            row[0] = (hv && lv) ? p[0] : 0ull;
            #pragma unroll
            for (int j = 1; j <= WS; j++)
                row[j] = hv ? p[j * C2] : 0ull;
            row[WS + 1] = (hv && rv) ? p[(WS + 1) * C2] : 0ull;

            #pragma unroll
            for (int oh = 0; oh < HS; oh++) {
                const int kh = r - oh;
                if (kh >= 0 && kh < 3) {
                    #pragma unroll
                    for (int ow = 0; ow < WS; ow++)
                        #pragma unroll
                        for (int kw = 0; kw < 3; kw++)
                            fma2(acc[oh][ow], row[ow + kw], wgt[kh][kw]);
                }
            }
        }
    }

    u64* o = out + ((size_t)((n * D_DIM + d) * H_DIM + h0) * W_DIM + w0) * C2 + lane;
    #pragma unroll
    for (int i = 0; i < HS; i++)
        #pragma unroll
        for (int j = 0; j < WS; j++)
            o[(i * W_DIM + j) * C2] = acc[i][j];
}

extern "C" void kernel_launch(void* const* d_in, const int* in_sizes, int n_in,
                              void* d_out, int out_size) {
    const u64* x = (const u64*)d_in[0];
    const u64* w = (const u64*)d_in[1];
    u64* o = (u64*)d_out;

    // total warps = N * D * HPAIR * WSEG = 4*16*56*16 = 57344
    const int total_warps = N_DIM * D_DIM * HPAIR * WSEG;
    dwconv3d_kernel<<<total_warps / WPB, TPB>>>(x, w, o);
}

// round 8
// speedup vs baseline: 1.5203x; 1.0181x over previous
#include <cuda_runtime.h>
#include <cstdint>

// Depthwise 3D conv 3x3x3, SAME, stride 1.
// x: (4,16,112,112,64) f32 NDHWC ; w: (3,3,3,1,64) f32
//
// R6: 4(H) x 7(W) warp tile, float2 channel lanes (one warp per pixel,
// 256B coalesced). kd-outer. L1 amp 5.79x (was 7.71x). Warp-uniform row
// skip for H edges (no per-load zero-fill), immediate-offset loads from a
// per-kd base pointer. __launch_bounds__(128,4) -> 16 warps/SM.

typedef unsigned long long u64;

#define W_DIM   112
#define H_DIM   112
#define D_DIM   16
#define N_DIM   4
#define C2      32                  // float2 channel groups = warp lanes
#define WS      7
#define HS      4
#define WSEG    (W_DIM / WS)        // 16
#define HT4     (H_DIM / HS)        // 28
#define WPB     4                   // warps per block
#define TPB     (WPB * 32)          // 128

#define ROW_F2    (W_DIM * C2)                 // u64 per H-row (3584)
#define SLICE_F2  (H_DIM * W_DIM * C2)         // u64 per D-slice
#define IMG_F2    ((size_t)D_DIM * SLICE_F2)   // u64 per batch n

__device__ __forceinline__ void fma2(u64& d, u64 a, u64 b) {
    asm("fma.rn.f32x2 %0, %1, %2, %0;" : "+l"(d) : "l"(a), "l"(b));
}

__global__ void __launch_bounds__(TPB, 4)
dwconv3d_kernel(const u64* __restrict__ xin,
                const u64* __restrict__ win,
                u64* __restrict__ out)
{
    const int lane = threadIdx.x & 31;
    const int gw   = blockIdx.x * WPB + (threadIdx.x >> 5);

    const int wseg = gw & (WSEG - 1);          // 16
    int t          = gw >> 4;
    const int ht   = t % HT4;                  // 28
    t             /= HT4;
    const int d    = t & (D_DIM - 1);          // 16
    const int n    = t >> 4;                   // 4

    const int h0 = ht * HS;
    const int w0 = wseg * WS;
    const bool lv = (wseg != 0);
    const bool rv = (wseg != WSEG - 1);
    const bool htop = (ht != 0);
    const bool hbot = (ht != HT4 - 1);

    const u64* wb = win + lane;
    // base at (n, d=0, h0-1, w0-1, lane); all further addressing is
    // compile-time immediates off per-kd slice pointers.
    const u64* xb = xin + (size_t)n * IMG_F2
                  + ((ptrdiff_t)(h0 - 1) * W_DIM + (w0 - 1)) * C2 + lane;

    u64 acc[HS][WS];
    #pragma unroll
    for (int i = 0; i < HS; i++)
        #pragma unroll
        for (int j = 0; j < WS; j++)
            acc[i][j] = 0ull;

    #pragma unroll
    for (int kd = 0; kd < 3; kd++) {
        const int id = d + kd - 1;
        if (id < 0 || id >= D_DIM) continue;       // warp-uniform

        u64 wgt[3][3];
        #pragma unroll
        for (int kh = 0; kh < 3; kh++)
            #pragma unroll
            for (int kw = 0; kw < 3; kw++)
                wgt[kh][kw] = wb[((kd * 3 + kh) * 3 + kw) * C2];

        const u64* xs = xb + (size_t)id * SLICE_F2;

        #pragma unroll
        for (int r = 0; r < HS + 2; r++) {
            // row validity: r==0 invalid only at top tile, r==HS+1 only at bottom
            if (r == 0      && !htop) continue;    // warp-uniform
            if (r == HS + 1 && !hbot) continue;

            const u64* p = xs + r * ROW_F2;        // immediate-folded

            u64 row[WS + 2];
            row[0] = lv ? p[0] : 0ull;
            #pragma unroll
            for (int j = 1; j <= WS; j++)
                row[j] = p[j * C2];
            row[WS + 1] = rv ? p[(WS + 1) * C2] : 0ull;

            #pragma unroll
            for (int oh = 0; oh < HS; oh++) {
                const int kh = r - 1 - oh + 1;     // kh = r - oh - ... ; see below
                // input row index rel: ih = h0 + r - 1 ; tap kh satisfies
                // ih = h0 + oh + kh - 1  =>  kh = r - oh
                const int k = r - oh;
                if (k >= 0 && k < 3) {
                    #pragma unroll
                    for (int ow = 0; ow < WS; ow++)
                        #pragma unroll
                        for (int kw = 0; kw < 3; kw++)
                            fma2(acc[oh][ow], row[ow + kw], wgt[k][kw]);
                }
            }
        }
    }

    u64* o = out + (size_t)n * IMG_F2 + (size_t)d * SLICE_F2
           + ((size_t)h0 * W_DIM + w0) * C2 + lane;
    #pragma unroll
    for (int i = 0; i < HS; i++)
        #pragma unroll
        for (int j = 0; j < WS; j++)
            o[(i * W_DIM + j) * C2] = acc[i][j];
}

extern "C" void kernel_launch(void* const* d_in, const int* in_sizes, int n_in,
                              void* d_out, int out_size) {
    const u64* x = (const u64*)d_in[0];
    const u64* w = (const u64*)d_in[1];
    u64* o = (u64*)d_out;

    // total warps = N * D * HT4 * WSEG = 4*16*28*16 = 28672
    const int total_warps = N_DIM * D_DIM * HT4 * WSEG;
    dwconv3d_kernel<<<total_warps / WPB, TPB>>>(x, w, o);
}